// round 2
// baseline (speedup 1.0000x reference)
#include <cuda_runtime.h>
#include <cuda_bf16.h>
#include <math.h>

// ---------------------------------------------------------------------------
// ViT encoder: B=8, C=3, H=W=256, P=8 -> N=1024 tokens, D=768, 8 layers,
// 12 heads x 64, MLP 3072. All fp32.
// ---------------------------------------------------------------------------

#define BB 8
#define NN_TOK 1024
#define DD 768
#define DEPTH 8
#define HEADS 12
#define DH 64
#define MLPD 3072
#define INNER 768
#define M_ROWS (BB * NN_TOK)          // 8192

// Scratch (device globals; allocation-free per harness rules)
__device__ float g_h[M_ROWS * DD];
__device__ float g_y[M_ROWS * DD];
__device__ float g_qkv[M_ROWS * 3 * INNER];
__device__ float g_s[(size_t)BB * HEADS * NN_TOK * NN_TOK];   // 402 MB
__device__ float g_o[M_ROWS * INNER];
__device__ float g_mlp[M_ROWS * MLPD];

__device__ __forceinline__ float gelu_f(float x) {
    return 0.5f * x * (1.0f + erff(x * 0.70710678118654752f));
}

// ---------------------------------------------------------------------------
// Patch embed: one block per token. patch = 3*8*8=192 inputs, 768 outputs.
// Adds conv bias + positional embedding.
// ---------------------------------------------------------------------------
__global__ void patch_embed_kernel(const float* __restrict__ x,
                                   const float* __restrict__ wc,
                                   const float* __restrict__ bc,
                                   const float* __restrict__ pos,
                                   float* __restrict__ h) {
    int bn = blockIdx.x;            // 0..8191
    int b = bn >> 10, n = bn & 1023;
    int py = n >> 5, px = n & 31;
    __shared__ float patch[192];
    int t = threadIdx.x;
    if (t < 192) {
        int c = t / 64, r = (t % 64) / 8, col = t % 8;
        patch[t] = x[(((size_t)b * 3 + c) * 256 + py * 8 + r) * 256 + px * 8 + col];
    }
    __syncthreads();
    for (int d = t; d < DD; d += 256) {
        float acc = bc[d];
        const float* wrow = wc + (size_t)d * 192;
        #pragma unroll 8
        for (int i = 0; i < 192; i++) acc += patch[i] * wrow[i];
        h[(size_t)bn * DD + d] = acc + pos[(size_t)n * DD + d];
    }
}

// ---------------------------------------------------------------------------
// LayerNorm: one block (256 thr) per row of 768.
// ---------------------------------------------------------------------------
__global__ void ln_kernel(const float* __restrict__ x,
                          const float* __restrict__ w,
                          const float* __restrict__ b,
                          float* __restrict__ y) {
    int row = blockIdx.x;
    const float* xr = x + (size_t)row * DD;
    __shared__ float red[256];
    int t = threadIdx.x;
    float v0 = xr[t], v1 = xr[t + 256], v2 = xr[t + 512];
    red[t] = v0 + v1 + v2;
    __syncthreads();
    #pragma unroll
    for (int s = 128; s > 0; s >>= 1) { if (t < s) red[t] += red[t + s]; __syncthreads(); }
    float mean = red[0] * (1.0f / DD);
    __syncthreads();
    float d0 = v0 - mean, d1 = v1 - mean, d2 = v2 - mean;
    red[t] = d0 * d0 + d1 * d1 + d2 * d2;
    __syncthreads();
    #pragma unroll
    for (int s = 128; s > 0; s >>= 1) { if (t < s) red[t] += red[t + s]; __syncthreads(); }
    float rstd = rsqrtf(red[0] * (1.0f / DD) + 1e-5f);
    float* yr = y + (size_t)row * DD;
    yr[t]       = d0 * rstd * w[t]       + b[t];
    yr[t + 256] = d1 * rstd * w[t + 256] + b[t + 256];
    yr[t + 512] = d2 * rstd * w[t + 512] + b[t + 512];
}

// ---------------------------------------------------------------------------
// Generic SGEMM: C[M,N] = epilogue(A[M,K] @ W[K,N]).
// 128x128 tile, BK=8, 256 threads, 8x8 per-thread microtile with split-tile
// (cols {tx*4, 64+tx*4}) layout for conflict-free vector LDS.
// M, N must be multiples of 128; K multiple of 8.
// ---------------------------------------------------------------------------
template <int WITH_BIAS, int WITH_GELU, int WITH_RES>
__global__ __launch_bounds__(256)
void gemm128(const float* __restrict__ A, const float* __restrict__ W,
             const float* __restrict__ bias, const float* __restrict__ res,
             float* __restrict__ C, int M, int N, int K) {
    __shared__ __align__(16) float As[8][128];
    __shared__ __align__(16) float Bs[8][128];
    int tid = threadIdx.x;
    int tx = tid & 15, ty = tid >> 4;
    int brow = blockIdx.y * 128, bcol = blockIdx.x * 128;

    float acc[8][8];
    #pragma unroll
    for (int i = 0; i < 8; i++)
        #pragma unroll
        for (int j = 0; j < 8; j++) acc[i][j] = 0.f;

    int arow = tid >> 1;               // 0..127
    int acol = (tid & 1) * 4;          // 0 or 4
    int bro  = tid >> 5;               // 0..7
    int bco  = (tid & 31) * 4;         // 0..124

    const float* Aptr = A + (size_t)(brow + arow) * K + acol;
    const float* Wptr = W + (size_t)bro * N + bcol + bco;

    for (int k0 = 0; k0 < K; k0 += 8) {
        float4 av = *(const float4*)(Aptr + k0);
        float4 bv = *(const float4*)(Wptr + (size_t)k0 * N);
        As[acol + 0][arow] = av.x;
        As[acol + 1][arow] = av.y;
        As[acol + 2][arow] = av.z;
        As[acol + 3][arow] = av.w;
        *(float4*)&Bs[bro][bco] = bv;
        __syncthreads();
        #pragma unroll
        for (int kk = 0; kk < 8; kk++) {
            float a[8], bb[8];
            *(float4*)(a)      = *(const float4*)&As[kk][ty * 4];
            *(float4*)(a + 4)  = *(const float4*)&As[kk][64 + ty * 4];
            *(float4*)(bb)     = *(const float4*)&Bs[kk][tx * 4];
            *(float4*)(bb + 4) = *(const float4*)&Bs[kk][64 + tx * 4];
            #pragma unroll
            for (int i = 0; i < 8; i++)
                #pragma unroll
                for (int j = 0; j < 8; j++) acc[i][j] += a[i] * bb[j];
        }
        __syncthreads();
    }

    #pragma unroll
    for (int i = 0; i < 8; i++) {
        int r = brow + ((i < 4) ? (ty * 4 + i) : (64 + ty * 4 + i - 4));
        #pragma unroll
        for (int jj = 0; jj < 2; jj++) {
            int cbase = bcol + ((jj == 0) ? (tx * 4) : (64 + tx * 4));
            float4 o;
            o.x = acc[i][jj * 4 + 0];
            o.y = acc[i][jj * 4 + 1];
            o.z = acc[i][jj * 4 + 2];
            o.w = acc[i][jj * 4 + 3];
            if (WITH_BIAS) {
                float4 bv = *(const float4*)&bias[cbase];
                o.x += bv.x; o.y += bv.y; o.z += bv.z; o.w += bv.w;
            }
            if (WITH_GELU) {
                o.x = gelu_f(o.x); o.y = gelu_f(o.y);
                o.z = gelu_f(o.z); o.w = gelu_f(o.w);
            }
            if (WITH_RES) {
                float4 rv = *(const float4*)&res[(size_t)r * N + cbase];
                o.x += rv.x; o.y += rv.y; o.z += rv.z; o.w += rv.w;
            }
            *(float4*)&C[(size_t)r * N + cbase] = o;
        }
    }
}

// ---------------------------------------------------------------------------
// Attention scores: S[z, m, n] = scale * sum_d Q[m,d]*K[n,d], z = b*12+head.
// 64x64 output tile per block, full K=64 in smem (transposed: [d][m]).
// ---------------------------------------------------------------------------
__global__ __launch_bounds__(256)
void qk_kernel(const float* __restrict__ qkv, float* __restrict__ S) {
    int z = blockIdx.z;
    int b = z / HEADS, hd = z % HEADS;
    const float* Q  = qkv + (size_t)b * NN_TOK * (3 * INNER) + hd * DH;
    const float* Kp = Q + INNER;
    __shared__ float Qs[DH][64];
    __shared__ float Ks[DH][64];
    int tid = threadIdx.x;
    int m0 = blockIdx.y * 64, n0 = blockIdx.x * 64;

    for (int t = tid; t < 1024; t += 256) {      // 64 rows x 16 float4
        int m = t >> 4, ds = (t & 15) * 4;
        float4 qv = *(const float4*)(Q  + (size_t)(m0 + m) * (3 * INNER) + ds);
        Qs[ds + 0][m] = qv.x; Qs[ds + 1][m] = qv.y;
        Qs[ds + 2][m] = qv.z; Qs[ds + 3][m] = qv.w;
        float4 kv = *(const float4*)(Kp + (size_t)(n0 + m) * (3 * INNER) + ds);
        Ks[ds + 0][m] = kv.x; Ks[ds + 1][m] = kv.y;
        Ks[ds + 2][m] = kv.z; Ks[ds + 3][m] = kv.w;
    }
    __syncthreads();

    int tx = tid & 15, ty = tid >> 4;
    float acc[4][4];
    #pragma unroll
    for (int i = 0; i < 4; i++)
        #pragma unroll
        for (int j = 0; j < 4; j++) acc[i][j] = 0.f;

    #pragma unroll 8
    for (int d = 0; d < DH; d++) {
        float a[4], bb[4];
        #pragma unroll
        for (int i = 0; i < 4; i++) { a[i] = Qs[d][ty * 4 + i]; bb[i] = Ks[d][tx * 4 + i]; }
        #pragma unroll
        for (int i = 0; i < 4; i++)
            #pragma unroll
            for (int j = 0; j < 4; j++) acc[i][j] += a[i] * bb[j];
    }
    const float scale = 0.125f;   // 1/sqrt(64)
    #pragma unroll
    for (int i = 0; i < 4; i++)
        #pragma unroll
        for (int j = 0; j < 4; j++)
            S[((size_t)z * NN_TOK + m0 + ty * 4 + i) * NN_TOK + n0 + tx * 4 + j] =
                acc[i][j] * scale;
}

// ---------------------------------------------------------------------------
// Softmax over last dim (1024) of S. One block per row.
// ---------------------------------------------------------------------------
__global__ void softmax_kernel(float* __restrict__ S) {
    size_t row = blockIdx.x;
    float* p = S + row * NN_TOK;
    int t = threadIdx.x;
    float v[4];
    #pragma unroll
    for (int i = 0; i < 4; i++) v[i] = p[t + i * 256];
    __shared__ float red[256];
    float mx = fmaxf(fmaxf(v[0], v[1]), fmaxf(v[2], v[3]));
    red[t] = mx;
    __syncthreads();
    #pragma unroll
    for (int s = 128; s > 0; s >>= 1) { if (t < s) red[t] = fmaxf(red[t], red[t + s]); __syncthreads(); }
    mx = red[0];
    __syncthreads();
    float sum = 0.f;
    #pragma unroll
    for (int i = 0; i < 4; i++) { v[i] = __expf(v[i] - mx); sum += v[i]; }
    red[t] = sum;
    __syncthreads();
    #pragma unroll
    for (int s = 128; s > 0; s >>= 1) { if (t < s) red[t] += red[t + s]; __syncthreads(); }
    float inv = 1.0f / red[0];
    #pragma unroll
    for (int i = 0; i < 4; i++) p[t + i * 256] = v[i] * inv;
}

// ---------------------------------------------------------------------------
// O = P @ V per (b, head). P [1024,1024], V [1024,64] (row stride 2304).
// 64-row tile per block (all 64 cols), BK=16.
// ---------------------------------------------------------------------------
__global__ __launch_bounds__(256)
void av_kernel(const float* __restrict__ S, const float* __restrict__ qkv,
               float* __restrict__ O) {
    int z = blockIdx.z;
    int b = z / HEADS, hd = z % HEADS;
    const float* P = S + (size_t)z * NN_TOK * NN_TOK;
    const float* V = qkv + (size_t)b * NN_TOK * (3 * INNER) + 2 * INNER + hd * DH;
    int m0 = blockIdx.y * 64;
    __shared__ __align__(16) float Ast[16][64];
    __shared__ __align__(16) float Bs[16][64];
    int tid = threadIdx.x;
    int tx = tid & 15, ty = tid >> 4;
    float acc[4][4];
    #pragma unroll
    for (int i = 0; i < 4; i++)
        #pragma unroll
        for (int j = 0; j < 4; j++) acc[i][j] = 0.f;

    int am = tid >> 2, ak = (tid & 3) * 4;      // 64 rows x 4 float4
    int bk = tid >> 4, bn = (tid & 15) * 4;     // 16 rows x 16 float4

    for (int k0 = 0; k0 < NN_TOK; k0 += 16) {
        float4 av = *(const float4*)(P + (size_t)(m0 + am) * NN_TOK + k0 + ak);
        Ast[ak + 0][am] = av.x; Ast[ak + 1][am] = av.y;
        Ast[ak + 2][am] = av.z; Ast[ak + 3][am] = av.w;
        float4 bv = *(const float4*)(V + (size_t)(k0 + bk) * (3 * INNER) + bn);
        *(float4*)&Bs[bk][bn] = bv;
        __syncthreads();
        #pragma unroll
        for (int kk = 0; kk < 16; kk++) {
            float a[4], bb[4];
            #pragma unroll
            for (int i = 0; i < 4; i++) { a[i] = Ast[kk][ty * 4 + i]; bb[i] = Bs[kk][tx * 4 + i]; }
            #pragma unroll
            for (int i = 0; i < 4; i++)
                #pragma unroll
                for (int j = 0; j < 4; j++) acc[i][j] += a[i] * bb[j];
        }
        __syncthreads();
    }
    #pragma unroll
    for (int i = 0; i < 4; i++)
        #pragma unroll
        for (int j = 0; j < 4; j++)
            O[(size_t)(b * NN_TOK + m0 + ty * 4 + i) * INNER + hd * DH + tx * 4 + j] =
                acc[i][j];
}

// ---------------------------------------------------------------------------
__global__ void copy_kernel(const float* __restrict__ src, float* __restrict__ dst) {
    int i = blockIdx.x * 256 + threadIdx.x;          // float4 index
    ((float4*)dst)[i] = ((const float4*)src)[i];
}

// ---------------------------------------------------------------------------
extern "C" void kernel_launch(void* const* d_in, const int* in_sizes, int n_in,
                              void* d_out, int out_size) {
    const float* x      = (const float*)d_in[0];
    const float* w_conv = (const float*)d_in[1];
    const float* b_conv = (const float*)d_in[2];
    const float* pos    = (const float*)d_in[3];
    const float* ln1_w  = (const float*)d_in[4];
    const float* ln1_b  = (const float*)d_in[5];
    const float* qkv_w  = (const float*)d_in[6];
    const float* out_w  = (const float*)d_in[7];
    const float* out_b  = (const float*)d_in[8];
    const float* ln2_w  = (const float*)d_in[9];
    const float* ln2_b  = (const float*)d_in[10];
    const float* w1     = (const float*)d_in[11];
    const float* b1     = (const float*)d_in[12];
    const float* w2     = (const float*)d_in[13];
    const float* b2     = (const float*)d_in[14];

    float *h, *y, *qkv, *s, *o, *mlp;
    cudaGetSymbolAddress((void**)&h,   g_h);
    cudaGetSymbolAddress((void**)&y,   g_y);
    cudaGetSymbolAddress((void**)&qkv, g_qkv);
    cudaGetSymbolAddress((void**)&s,   g_s);
    cudaGetSymbolAddress((void**)&o,   g_o);
    cudaGetSymbolAddress((void**)&mlp, g_mlp);

    patch_embed_kernel<<<M_ROWS, 256>>>(x, w_conv, b_conv, pos, h);

    for (int l = 0; l < DEPTH; l++) {
        const float* l1w = ln1_w + (size_t)l * DD;
        const float* l1b = ln1_b + (size_t)l * DD;
        const float* qw  = qkv_w + (size_t)l * DD * (3 * INNER);
        const float* ow  = out_w + (size_t)l * INNER * DD;
        const float* ob  = out_b + (size_t)l * DD;
        const float* l2w = ln2_w + (size_t)l * DD;
        const float* l2b = ln2_b + (size_t)l * DD;
        const float* W1  = w1 + (size_t)l * DD * MLPD;
        const float* B1  = b1 + (size_t)l * MLPD;
        const float* W2  = w2 + (size_t)l * MLPD * DD;
        const float* B2  = b2 + (size_t)l * DD;

        // PreNorm + QKV projection
        ln_kernel<<<M_ROWS, 256>>>(h, l1w, l1b, y);
        gemm128<0, 0, 0><<<dim3((3 * INNER) / 128, M_ROWS / 128), 256>>>(
            y, qw, nullptr, nullptr, qkv, M_ROWS, 3 * INNER, DD);

        // Attention
        qk_kernel<<<dim3(NN_TOK / 64, NN_TOK / 64, BB * HEADS), 256>>>(qkv, s);
        softmax_kernel<<<BB * HEADS * NN_TOK, 256>>>(s);
        av_kernel<<<dim3(1, NN_TOK / 64, BB * HEADS), 256>>>(s, qkv, o);

        // Output projection + residual
        gemm128<1, 0, 1><<<dim3(DD / 128, M_ROWS / 128), 256>>>(
            o, ow, ob, h, h, M_ROWS, DD, INNER);

        // PreNorm + FFN
        ln_kernel<<<M_ROWS, 256>>>(h, l2w, l2b, y);
        gemm128<1, 1, 0><<<dim3(MLPD / 128, M_ROWS / 128), 256>>>(
            y, W1, B1, nullptr, mlp, M_ROWS, MLPD, DD);
        gemm128<1, 0, 1><<<dim3(DD / 128, M_ROWS / 128), 256>>>(
            mlp, W2, B2, h, h, M_ROWS, DD, MLPD);
    }

    // Final output
    copy_kernel<<<(M_ROWS * DD) / (256 * 4), 256>>>(h, (float*)d_out);
}

// round 3
// speedup vs baseline: 1.7618x; 1.7618x over previous
#include <cuda_runtime.h>
#include <cuda_bf16.h>
#include <math.h>

// ---------------------------------------------------------------------------
// ViT encoder: B=8, C=3, H=W=256, P=8 -> N=1024 tokens, D=768, 8 layers,
// 12 heads x 64, MLP 3072. GEMMs on tensor cores via tf32 mma.sync.
// ---------------------------------------------------------------------------

#define BB 8
#define NN_TOK 1024
#define DD 768
#define DEPTH 8
#define HEADS 12
#define DH 64
#define MLPD 3072
#define INNER 768
#define M_ROWS (BB * NN_TOK)          // 8192

// Scratch (device globals; allocation-free per harness rules)
__device__ float g_h[M_ROWS * DD];
__device__ float g_y[M_ROWS * DD];
__device__ float g_qkv[M_ROWS * 3 * INNER];
__device__ float g_s[(size_t)BB * HEADS * NN_TOK * NN_TOK];   // 402 MB
__device__ float g_o[M_ROWS * INNER];
__device__ float g_mlp[M_ROWS * MLPD];

__device__ __forceinline__ float gelu_f(float x) {
    return 0.5f * x * (1.0f + erff(x * 0.70710678118654752f));
}

__device__ __forceinline__ float to_tf32(float x) {
    unsigned u;
    asm("cvt.rna.tf32.f32 %0, %1;" : "=r"(u) : "f"(x));
    return __uint_as_float(u);
}

__device__ __forceinline__ void mma_tf32(float* d, const unsigned* a, const unsigned* b) {
    asm volatile(
        "mma.sync.aligned.m16n8k8.row.col.f32.tf32.tf32.f32 "
        "{%0,%1,%2,%3}, {%4,%5,%6,%7}, {%8,%9}, {%0,%1,%2,%3};\n"
        : "+f"(d[0]), "+f"(d[1]), "+f"(d[2]), "+f"(d[3])
        : "r"(a[0]), "r"(a[1]), "r"(a[2]), "r"(a[3]), "r"(b[0]), "r"(b[1]));
}

// ---------------------------------------------------------------------------
// Patch embed
// ---------------------------------------------------------------------------
__global__ void patch_embed_kernel(const float* __restrict__ x,
                                   const float* __restrict__ wc,
                                   const float* __restrict__ bc,
                                   const float* __restrict__ pos,
                                   float* __restrict__ h) {
    int bn = blockIdx.x;
    int b = bn >> 10, n = bn & 1023;
    int py = n >> 5, px = n & 31;
    __shared__ float patch[192];
    int t = threadIdx.x;
    if (t < 192) {
        int c = t / 64, r = (t % 64) / 8, col = t % 8;
        patch[t] = x[(((size_t)b * 3 + c) * 256 + py * 8 + r) * 256 + px * 8 + col];
    }
    __syncthreads();
    for (int d = t; d < DD; d += 256) {
        float acc = bc[d];
        const float* wrow = wc + (size_t)d * 192;
        #pragma unroll 8
        for (int i = 0; i < 192; i++) acc += patch[i] * wrow[i];
        h[(size_t)bn * DD + d] = acc + pos[(size_t)n * DD + d];
    }
}

// ---------------------------------------------------------------------------
// LayerNorm
// ---------------------------------------------------------------------------
__global__ void ln_kernel(const float* __restrict__ x,
                          const float* __restrict__ w,
                          const float* __restrict__ b,
                          float* __restrict__ y) {
    int row = blockIdx.x;
    const float* xr = x + (size_t)row * DD;
    __shared__ float red[256];
    int t = threadIdx.x;
    float v0 = xr[t], v1 = xr[t + 256], v2 = xr[t + 512];
    red[t] = v0 + v1 + v2;
    __syncthreads();
    #pragma unroll
    for (int s = 128; s > 0; s >>= 1) { if (t < s) red[t] += red[t + s]; __syncthreads(); }
    float mean = red[0] * (1.0f / DD);
    __syncthreads();
    float d0 = v0 - mean, d1 = v1 - mean, d2 = v2 - mean;
    red[t] = d0 * d0 + d1 * d1 + d2 * d2;
    __syncthreads();
    #pragma unroll
    for (int s = 128; s > 0; s >>= 1) { if (t < s) red[t] += red[t + s]; __syncthreads(); }
    float rstd = rsqrtf(red[0] * (1.0f / DD) + 1e-5f);
    float* yr = y + (size_t)row * DD;
    yr[t]       = d0 * rstd * w[t]       + b[t];
    yr[t + 256] = d1 * rstd * w[t + 256] + b[t + 256];
    yr[t + 512] = d2 * rstd * w[t + 512] + b[t + 512];
}

// ---------------------------------------------------------------------------
// Templated tf32 tensor-core GEMM.
// Tile: BM = WM*64 rows, BN = WN*32 cols; 8 warps (WM*WN == 8), each warp
// computes a 64x32 tile via 4x4 grid of m16n8k8 mma. BK = 16.
// ATT: 0 = plain (gridDim.z==1), 1 = Q@K^T per (b,head), 2 = P@V per (b,head).
// TRANSB: B given as [n][k] row-major (transpose-loaded).
// ---------------------------------------------------------------------------
template <int WM, int WN, int TRANSB, int BIAS, int GELU, int RES, int SCALE, int ATT>
__global__ __launch_bounds__(256)
void mma_gemm(const float* __restrict__ A, const float* __restrict__ Bm,
              const float* __restrict__ bias, const float* __restrict__ res,
              float* __restrict__ C,
              int K, int lda, int ldb, int ldc, float alpha) {
    constexpr int BM = WM * 64;
    constexpr int BN = WN * 32;
    constexpr int PA = BM + 8;      // pitch ≡ 8 (mod 32) -> conflict-free frags
    constexpr int PB = BN + 8;

    __shared__ float As[16][PA];
    __shared__ float Bs[16][PB];

    if (ATT == 1) {
        int z = blockIdx.z, b = z / HEADS, hd = z % HEADS;
        A  += (size_t)b * NN_TOK * (3 * INNER) + hd * DH;            // Q
        Bm += (size_t)b * NN_TOK * (3 * INNER) + INNER + hd * DH;    // K
        C  += (size_t)z * NN_TOK * NN_TOK;
    } else if (ATT == 2) {
        int z = blockIdx.z, b = z / HEADS, hd = z % HEADS;
        A  += (size_t)z * NN_TOK * NN_TOK;                           // P
        Bm += (size_t)b * NN_TOK * (3 * INNER) + 2 * INNER + hd * DH;// V
        C  += (size_t)b * NN_TOK * INNER + hd * DH;                  // O
    }

    int tid = threadIdx.x;
    int wid = tid >> 5, lane = tid & 31;
    int g = lane >> 2, tg = lane & 3;
    int warp_m = (wid / WN) * 64;
    int warp_n = (wid % WN) * 32;
    int bm0 = blockIdx.y * BM, bn0 = blockIdx.x * BN;

    float acc[4][4][4];
    #pragma unroll
    for (int i = 0; i < 4; i++)
        #pragma unroll
        for (int j = 0; j < 4; j++)
            #pragma unroll
            for (int r = 0; r < 4; r++) acc[i][j][r] = 0.f;

    constexpr int ACNT = BM / 64;                // float4 loads per thread (A)
    constexpr int BCNT = BN / 64 > 0 ? BN / 64 : 1;
    float4 ar[ACNT];
    float4 br[BCNT];

    auto loadA = [&](int k0) {
        #pragma unroll
        for (int i = 0; i < ACNT; i++) {
            int idx = tid + i * 256;
            int m = idx & (BM - 1);
            int kq = idx / BM;                   // 0..3
            ar[i] = *(const float4*)(A + (size_t)(bm0 + m) * lda + k0 + kq * 4);
        }
    };
    auto storeA = [&]() {
        #pragma unroll
        for (int i = 0; i < ACNT; i++) {
            int idx = tid + i * 256;
            int m = idx & (BM - 1);
            int kq = idx / BM;
            As[kq * 4 + 0][m] = to_tf32(ar[i].x);
            As[kq * 4 + 1][m] = to_tf32(ar[i].y);
            As[kq * 4 + 2][m] = to_tf32(ar[i].z);
            As[kq * 4 + 3][m] = to_tf32(ar[i].w);
        }
    };
    auto loadB = [&](int k0) {
        #pragma unroll
        for (int i = 0; i < BCNT; i++) {
            int idx = tid + i * 256;
            if (TRANSB) {
                int n = idx & (BN - 1);
                int kq = idx / BN;
                br[i] = *(const float4*)(Bm + (size_t)(bn0 + n) * ldb + k0 + kq * 4);
            } else {
                int n4 = idx % (BN / 4);
                int k  = idx / (BN / 4);
                br[i] = *(const float4*)(Bm + (size_t)(k0 + k) * ldb + bn0 + n4 * 4);
            }
        }
    };
    auto storeB = [&]() {
        #pragma unroll
        for (int i = 0; i < BCNT; i++) {
            int idx = tid + i * 256;
            if (TRANSB) {
                int n = idx & (BN - 1);
                int kq = idx / BN;
                Bs[kq * 4 + 0][n] = to_tf32(br[i].x);
                Bs[kq * 4 + 1][n] = to_tf32(br[i].y);
                Bs[kq * 4 + 2][n] = to_tf32(br[i].z);
                Bs[kq * 4 + 3][n] = to_tf32(br[i].w);
            } else {
                int n4 = idx % (BN / 4);
                int k  = idx / (BN / 4);
                float4 v;
                v.x = to_tf32(br[i].x); v.y = to_tf32(br[i].y);
                v.z = to_tf32(br[i].z); v.w = to_tf32(br[i].w);
                *(float4*)&Bs[k][n4 * 4] = v;
            }
        }
    };
    auto compute = [&]() {
        #pragma unroll
        for (int ks = 0; ks < 2; ks++) {
            int k8 = ks * 8;
            unsigned bf[4][2];
            #pragma unroll
            for (int tj = 0; tj < 4; tj++) {
                int nb = warp_n + tj * 8 + g;
                bf[tj][0] = __float_as_uint(Bs[k8 + tg][nb]);
                bf[tj][1] = __float_as_uint(Bs[k8 + tg + 4][nb]);
            }
            #pragma unroll
            for (int ti = 0; ti < 4; ti++) {
                int mb = warp_m + ti * 16 + g;
                unsigned af[4];
                af[0] = __float_as_uint(As[k8 + tg][mb]);
                af[1] = __float_as_uint(As[k8 + tg][mb + 8]);
                af[2] = __float_as_uint(As[k8 + tg + 4][mb]);
                af[3] = __float_as_uint(As[k8 + tg + 4][mb + 8]);
                #pragma unroll
                for (int tj = 0; tj < 4; tj++)
                    mma_tf32(acc[ti][tj], af, bf[tj]);
            }
        }
    };

    // Prologue + software-pipelined mainloop
    loadA(0); loadB(0);
    storeA(); storeB();
    __syncthreads();
    for (int k0 = 16; k0 < K; k0 += 16) {
        loadA(k0); loadB(k0);
        compute();
        __syncthreads();
        storeA(); storeB();
        __syncthreads();
    }
    compute();

    // Epilogue
    #pragma unroll
    for (int ti = 0; ti < 4; ti++) {
        #pragma unroll
        for (int tj = 0; tj < 4; tj++) {
            int r0 = bm0 + warp_m + ti * 16 + g;
            int r1 = r0 + 8;
            int cc = bn0 + warp_n + tj * 8 + tg * 2;
            float v0 = acc[ti][tj][0], v1 = acc[ti][tj][1];
            float v2 = acc[ti][tj][2], v3 = acc[ti][tj][3];
            if (SCALE) { v0 *= alpha; v1 *= alpha; v2 *= alpha; v3 *= alpha; }
            if (BIAS) {
                float b0 = bias[cc], b1 = bias[cc + 1];
                v0 += b0; v1 += b1; v2 += b0; v3 += b1;
            }
            if (GELU) {
                v0 = gelu_f(v0); v1 = gelu_f(v1);
                v2 = gelu_f(v2); v3 = gelu_f(v3);
            }
            if (RES) {
                const float* r0p = res + (size_t)r0 * ldc + cc;
                const float* r1p = res + (size_t)r1 * ldc + cc;
                v0 += r0p[0]; v1 += r0p[1];
                v2 += r1p[0]; v3 += r1p[1];
            }
            float2 o0 = {v0, v1}, o1 = {v2, v3};
            *(float2*)&C[(size_t)r0 * ldc + cc] = o0;
            *(float2*)&C[(size_t)r1 * ldc + cc] = o1;
        }
    }
}

// ---------------------------------------------------------------------------
// Softmax over last dim (1024). One block per row.
// ---------------------------------------------------------------------------
__global__ void softmax_kernel(float* __restrict__ S) {
    size_t row = blockIdx.x;
    float* p = S + row * NN_TOK;
    int t = threadIdx.x;
    float v[4];
    #pragma unroll
    for (int i = 0; i < 4; i++) v[i] = p[t + i * 256];
    __shared__ float red[256];
    float mx = fmaxf(fmaxf(v[0], v[1]), fmaxf(v[2], v[3]));
    red[t] = mx;
    __syncthreads();
    #pragma unroll
    for (int s = 128; s > 0; s >>= 1) { if (t < s) red[t] = fmaxf(red[t], red[t + s]); __syncthreads(); }
    mx = red[0];
    __syncthreads();
    float sum = 0.f;
    #pragma unroll
    for (int i = 0; i < 4; i++) { v[i] = __expf(v[i] - mx); sum += v[i]; }
    red[t] = sum;
    __syncthreads();
    #pragma unroll
    for (int s = 128; s > 0; s >>= 1) { if (t < s) red[t] += red[t + s]; __syncthreads(); }
    float inv = 1.0f / red[0];
    #pragma unroll
    for (int i = 0; i < 4; i++) p[t + i * 256] = v[i] * inv;
}

// ---------------------------------------------------------------------------
__global__ void copy_kernel(const float* __restrict__ src, float* __restrict__ dst) {
    int i = blockIdx.x * 256 + threadIdx.x;
    ((float4*)dst)[i] = ((const float4*)src)[i];
}

// ---------------------------------------------------------------------------
extern "C" void kernel_launch(void* const* d_in, const int* in_sizes, int n_in,
                              void* d_out, int out_size) {
    const float* x      = (const float*)d_in[0];
    const float* w_conv = (const float*)d_in[1];
    const float* b_conv = (const float*)d_in[2];
    const float* pos    = (const float*)d_in[3];
    const float* ln1_w  = (const float*)d_in[4];
    const float* ln1_b  = (const float*)d_in[5];
    const float* qkv_w  = (const float*)d_in[6];
    const float* out_w  = (const float*)d_in[7];
    const float* out_b  = (const float*)d_in[8];
    const float* ln2_w  = (const float*)d_in[9];
    const float* ln2_b  = (const float*)d_in[10];
    const float* w1     = (const float*)d_in[11];
    const float* b1     = (const float*)d_in[12];
    const float* w2     = (const float*)d_in[13];
    const float* b2     = (const float*)d_in[14];

    float *h, *y, *qkv, *s, *o, *mlp;
    cudaGetSymbolAddress((void**)&h,   g_h);
    cudaGetSymbolAddress((void**)&y,   g_y);
    cudaGetSymbolAddress((void**)&qkv, g_qkv);
    cudaGetSymbolAddress((void**)&s,   g_s);
    cudaGetSymbolAddress((void**)&o,   g_o);
    cudaGetSymbolAddress((void**)&mlp, g_mlp);

    patch_embed_kernel<<<M_ROWS, 256>>>(x, w_conv, b_conv, pos, h);

    for (int l = 0; l < DEPTH; l++) {
        const float* l1w = ln1_w + (size_t)l * DD;
        const float* l1b = ln1_b + (size_t)l * DD;
        const float* qw  = qkv_w + (size_t)l * DD * (3 * INNER);
        const float* ow  = out_w + (size_t)l * INNER * DD;
        const float* ob  = out_b + (size_t)l * DD;
        const float* l2w = ln2_w + (size_t)l * DD;
        const float* l2b = ln2_b + (size_t)l * DD;
        const float* W1  = w1 + (size_t)l * DD * MLPD;
        const float* B1  = b1 + (size_t)l * MLPD;
        const float* W2  = w2 + (size_t)l * MLPD * DD;
        const float* B2  = b2 + (size_t)l * DD;

        // PreNorm + QKV projection
        ln_kernel<<<M_ROWS, 256>>>(h, l1w, l1b, y);
        mma_gemm<2, 4, 0, 0, 0, 0, 0, 0><<<dim3((3 * INNER) / 128, M_ROWS / 128), 256>>>(
            y, qw, nullptr, nullptr, qkv, DD, DD, 3 * INNER, 3 * INNER, 1.f);

        // Attention: S = scale * Q @ K^T
        mma_gemm<2, 4, 1, 0, 0, 0, 1, 1><<<dim3(NN_TOK / 128, NN_TOK / 128, BB * HEADS), 256>>>(
            qkv, qkv, nullptr, nullptr, s, DH, 3 * INNER, 3 * INNER, NN_TOK, 0.125f);

        softmax_kernel<<<BB * HEADS * NN_TOK, 256>>>(s);

        // O = P @ V  (BM=256, BN=64)
        mma_gemm<4, 2, 0, 0, 0, 0, 0, 2><<<dim3(1, NN_TOK / 256, BB * HEADS), 256>>>(
            s, qkv, nullptr, nullptr, o, NN_TOK, NN_TOK, 3 * INNER, INNER, 1.f);

        // Output projection + residual
        mma_gemm<2, 4, 0, 1, 0, 1, 0, 0><<<dim3(DD / 128, M_ROWS / 128), 256>>>(
            o, ow, ob, h, h, INNER, INNER, DD, DD, 1.f);

        // PreNorm + FFN
        ln_kernel<<<M_ROWS, 256>>>(h, l2w, l2b, y);
        mma_gemm<2, 4, 0, 1, 1, 0, 0, 0><<<dim3(MLPD / 128, M_ROWS / 128), 256>>>(
            y, W1, B1, nullptr, mlp, DD, DD, MLPD, MLPD, 1.f);
        mma_gemm<2, 4, 0, 1, 0, 1, 0, 0><<<dim3(DD / 128, M_ROWS / 128), 256>>>(
            mlp, W2, B2, h, h, MLPD, MLPD, DD, DD, 1.f);
    }

    copy_kernel<<<(M_ROWS * DD) / (256 * 4), 256>>>(h, (float*)d_out);
}

// round 5
// speedup vs baseline: 2.5632x; 1.4549x over previous
#include <cuda_runtime.h>
#include <cuda_bf16.h>
#include <math.h>

// ---------------------------------------------------------------------------
// ViT encoder: B=8, N=1024 tokens, D=768, 8 layers, 12 heads x 64, MLP 3072.
// tf32 mma.sync GEMMs (cp.async 4-stage pipeline) + fused flash attention.
// ---------------------------------------------------------------------------

#define BB 8
#define NN_TOK 1024
#define DD 768
#define DEPTH 8
#define HEADS 12
#define DH 64
#define MLPD 3072
#define INNER 768
#define M_ROWS (BB * NN_TOK)          // 8192
#define QKV_LD (3 * INNER)            // 2304

// Scratch (device globals; allocation-free per harness rules)
__device__ float g_h[M_ROWS * DD];
__device__ float g_y[M_ROWS * DD];
__device__ float g_qkv[M_ROWS * QKV_LD];
__device__ float g_o[M_ROWS * INNER];
__device__ float g_mlp[M_ROWS * MLPD];

__device__ __forceinline__ float gelu_f(float x) {
    return 0.5f * x * (1.0f + erff(x * 0.70710678118654752f));
}
__device__ __forceinline__ unsigned tf32u(float x) {
    unsigned u; asm("cvt.rna.tf32.f32 %0, %1;" : "=r"(u) : "f"(x)); return u;
}
__device__ __forceinline__ float tf32f(float x) {
    unsigned u; asm("cvt.rna.tf32.f32 %0, %1;" : "=r"(u) : "f"(x));
    return __uint_as_float(u);
}
__device__ __forceinline__ void mma_tf32(float* d, const unsigned* a, const unsigned* b) {
    asm volatile(
        "mma.sync.aligned.m16n8k8.row.col.f32.tf32.tf32.f32 "
        "{%0,%1,%2,%3}, {%4,%5,%6,%7}, {%8,%9}, {%0,%1,%2,%3};\n"
        : "+f"(d[0]), "+f"(d[1]), "+f"(d[2]), "+f"(d[3])
        : "r"(a[0]), "r"(a[1]), "r"(a[2]), "r"(a[3]), "r"(b[0]), "r"(b[1]));
}
__device__ __forceinline__ void cp_async16(void* s, const void* g) {
    unsigned sa = (unsigned)__cvta_generic_to_shared(s);
    asm volatile("cp.async.cg.shared.global [%0], [%1], 16;\n" :: "r"(sa), "l"(g));
}
#define CP_COMMIT() asm volatile("cp.async.commit_group;\n" ::: "memory")
#define CP_WAIT(n)  asm volatile("cp.async.wait_group %0;\n" :: "n"(n) : "memory")

// ---------------------------------------------------------------------------
// Patch embed
// ---------------------------------------------------------------------------
__global__ void patch_embed_kernel(const float* __restrict__ x,
                                   const float* __restrict__ wc,
                                   const float* __restrict__ bc,
                                   const float* __restrict__ pos,
                                   float* __restrict__ h) {
    int bn = blockIdx.x;
    int b = bn >> 10, n = bn & 1023;
    int py = n >> 5, px = n & 31;
    __shared__ float patch[192];
    int t = threadIdx.x;
    if (t < 192) {
        int c = t / 64, r = (t % 64) / 8, col = t % 8;
        patch[t] = x[(((size_t)b * 3 + c) * 256 + py * 8 + r) * 256 + px * 8 + col];
    }
    __syncthreads();
    for (int d = t; d < DD; d += 256) {
        float acc = bc[d];
        const float* wrow = wc + (size_t)d * 192;
        #pragma unroll 8
        for (int i = 0; i < 192; i++) acc += patch[i] * wrow[i];
        h[(size_t)bn * DD + d] = acc + pos[(size_t)n * DD + d];
    }
}

// ---------------------------------------------------------------------------
// LayerNorm
// ---------------------------------------------------------------------------
__global__ void ln_kernel(const float* __restrict__ x,
                          const float* __restrict__ w,
                          const float* __restrict__ b,
                          float* __restrict__ y) {
    int row = blockIdx.x;
    const float* xr = x + (size_t)row * DD;
    __shared__ float red[256];
    int t = threadIdx.x;
    float v0 = xr[t], v1 = xr[t + 256], v2 = xr[t + 512];
    red[t] = v0 + v1 + v2;
    __syncthreads();
    #pragma unroll
    for (int s = 128; s > 0; s >>= 1) { if (t < s) red[t] += red[t + s]; __syncthreads(); }
    float mean = red[0] * (1.0f / DD);
    __syncthreads();
    float d0 = v0 - mean, d1 = v1 - mean, d2 = v2 - mean;
    red[t] = d0 * d0 + d1 * d1 + d2 * d2;
    __syncthreads();
    #pragma unroll
    for (int s = 128; s > 0; s >>= 1) { if (t < s) red[t] += red[t + s]; __syncthreads(); }
    float rstd = rsqrtf(red[0] * (1.0f / DD) + 1e-5f);
    float* yr = y + (size_t)row * DD;
    yr[t]       = d0 * rstd * w[t]       + b[t];
    yr[t + 256] = d1 * rstd * w[t + 256] + b[t + 256];
    yr[t + 512] = d2 * rstd * w[t + 512] + b[t + 512];
}

// ---------------------------------------------------------------------------
// tf32 GEMM: C[M,N] = epi(A[M,K] @ W[K,N]). BM=BN=128, BK=16, 4-stage cp.async.
// 256 threads, 8 warps (2x4), warp tile 64x32, m16n8k8.
// Layouts: As[stage][m][20] (row-major, pitch 20), Bs[stage][k][136].
// ---------------------------------------------------------------------------
#define GSTAGES 4
#define GEMM_SMEM ((GSTAGES * 128 * 20 + GSTAGES * 16 * 136) * 4)

template <int BIAS, int GELU, int RES, int TF32OUT>
__global__ __launch_bounds__(256)
void mma_gemm(const float* __restrict__ A, const float* __restrict__ W,
              const float* __restrict__ bias, const float* __restrict__ res,
              float* __restrict__ C, int K, int N) {
    extern __shared__ float smem[];
    float (*As)[128][20] = (float(*)[128][20])smem;
    float (*Bs)[16][136] = (float(*)[16][136])(smem + GSTAGES * 128 * 20);

    int tid = threadIdx.x, wid = tid >> 5, lane = tid & 31;
    int g = lane >> 2, tg = lane & 3;
    int warp_m = (wid >> 2) * 64, warp_n = (wid & 3) * 32;
    int bm0 = blockIdx.y * 128, bn0 = blockIdx.x * 128;

    float acc[4][4][4];
    #pragma unroll
    for (int i = 0; i < 4; i++)
        #pragma unroll
        for (int j = 0; j < 4; j++)
            #pragma unroll
            for (int r = 0; r < 4; r++) acc[i][j][r] = 0.f;

    const float* Abase = A + (size_t)bm0 * K;
    const float* Wbase = W + bn0;

    int am = tid >> 2, ak4 = tid & 3;          // A: 128 rows x 4 quads
    int bk = tid >> 5, bn4 = tid & 31;         // B: 8 rows x 32 quads (x2)

    auto issue = [&](int tile, int s) {
        int k0 = tile * 16;
        cp_async16(&As[s][am][ak4 * 4],       Abase + (size_t)am * K + k0 + ak4 * 4);
        cp_async16(&As[s][am + 64][ak4 * 4],  Abase + (size_t)(am + 64) * K + k0 + ak4 * 4);
        cp_async16(&Bs[s][bk][bn4 * 4],       Wbase + (size_t)(k0 + bk) * N + bn4 * 4);
        cp_async16(&Bs[s][bk + 8][bn4 * 4],   Wbase + (size_t)(k0 + bk + 8) * N + bn4 * 4);
        CP_COMMIT();
    };

    int niter = K / 16;
    issue(0, 0); issue(1, 1); issue(2, 2);

    for (int i = 0; i < niter; i++) {
        int rem = niter - i;
        if (rem >= 3)      CP_WAIT(2);
        else if (rem == 2) CP_WAIT(1);
        else               CP_WAIT(0);
        __syncthreads();
        if (i + 3 < niter) issue(i + 3, (i + 3) & 3);
        int s = i & 3;
        #pragma unroll
        for (int ks = 0; ks < 2; ks++) {
            int k8 = ks * 8;
            unsigned bf[4][2];
            #pragma unroll
            for (int tj = 0; tj < 4; tj++) {
                int nb = warp_n + tj * 8 + g;
                bf[tj][0] = tf32u(Bs[s][k8 + tg][nb]);
                bf[tj][1] = tf32u(Bs[s][k8 + tg + 4][nb]);
            }
            #pragma unroll
            for (int ti = 0; ti < 4; ti++) {
                int mb = warp_m + ti * 16 + g;
                unsigned af[4];
                af[0] = tf32u(As[s][mb][k8 + tg]);
                af[1] = tf32u(As[s][mb + 8][k8 + tg]);
                af[2] = tf32u(As[s][mb][k8 + tg + 4]);
                af[3] = tf32u(As[s][mb + 8][k8 + tg + 4]);
                #pragma unroll
                for (int tj = 0; tj < 4; tj++)
                    mma_tf32(acc[ti][tj], af, bf[tj]);
            }
        }
    }

    #pragma unroll
    for (int ti = 0; ti < 4; ti++) {
        #pragma unroll
        for (int tj = 0; tj < 4; tj++) {
            int r0 = bm0 + warp_m + ti * 16 + g;
            int r1 = r0 + 8;
            int cc = bn0 + warp_n + tj * 8 + tg * 2;
            float v0 = acc[ti][tj][0], v1 = acc[ti][tj][1];
            float v2 = acc[ti][tj][2], v3 = acc[ti][tj][3];
            if (BIAS) {
                float b0 = bias[cc], b1 = bias[cc + 1];
                v0 += b0; v1 += b1; v2 += b0; v3 += b1;
            }
            if (GELU) {
                v0 = gelu_f(v0); v1 = gelu_f(v1);
                v2 = gelu_f(v2); v3 = gelu_f(v3);
            }
            if (RES) {
                const float* p0 = res + (size_t)r0 * N + cc;
                const float* p1 = res + (size_t)r1 * N + cc;
                v0 += p0[0]; v1 += p0[1]; v2 += p1[0]; v3 += p1[1];
            }
            if (TF32OUT) {
                v0 = tf32f(v0); v1 = tf32f(v1); v2 = tf32f(v2); v3 = tf32f(v3);
            }
            float2 o0 = {v0, v1}, o1 = {v2, v3};
            *(float2*)&C[(size_t)r0 * N + cc] = o0;
            *(float2*)&C[(size_t)r1 * N + cc] = o1;
        }
    }
}

// ---------------------------------------------------------------------------
// Fused flash attention. One block = one (b, head, 128-row Q tile).
// 8 warps x 16 Q rows. Loop over 16 KV tiles of 64. Online softmax.
// qkv values are pre-rounded to tf32 by the qkv GEMM epilogue.
// Smem: Qs[128][68], Ks[64][68], Vs[64][72], Ps[128][68].
// ---------------------------------------------------------------------------
#define FLASH_SMEM ((128 * 68 + 64 * 68 + 64 * 72 + 128 * 68) * 4)

__global__ __launch_bounds__(256)
void flash_attn(const float* __restrict__ qkv, float* __restrict__ O) {
    extern __shared__ float fs[];
    float (*Qs)[68] = (float(*)[68])fs;
    float (*Ks)[68] = (float(*)[68])(fs + 128 * 68);
    float (*Vs)[72] = (float(*)[72])(fs + 128 * 68 + 64 * 68);
    float (*Ps)[68] = (float(*)[68])(fs + 128 * 68 + 64 * 68 + 64 * 72);

    int z = blockIdx.y, b = z / HEADS, hd = z % HEADS;
    const float* Qp = qkv + (size_t)b * NN_TOK * QKV_LD + hd * DH;
    const float* Kp = Qp + INNER;
    const float* Vp = Qp + 2 * INNER;
    int q0 = blockIdx.x * 128;

    int tid = threadIdx.x, wid = tid >> 5, lane = tid & 31;
    int g = lane >> 2, tg = lane & 3;
    int warp_m = wid * 16;

    int lr = tid >> 4, ld4 = tid & 15;     // 16 rows x 16 quads per 256-pass

    auto issueK = [&](int j) {
        #pragma unroll
        for (int i = 0; i < 4; i++)
            cp_async16(&Ks[lr + i * 16][ld4 * 4],
                       Kp + (size_t)(j * 64 + lr + i * 16) * QKV_LD + ld4 * 4);
        CP_COMMIT();
    };
    auto issueV = [&](int j) {
        #pragma unroll
        for (int i = 0; i < 4; i++)
            cp_async16(&Vs[lr + i * 16][ld4 * 4],
                       Vp + (size_t)(j * 64 + lr + i * 16) * QKV_LD + ld4 * 4);
        CP_COMMIT();
    };

    // Group 0: Q + K0.  Group 1: V0.
    #pragma unroll
    for (int i = 0; i < 8; i++)
        cp_async16(&Qs[lr + i * 16][ld4 * 4],
                   Qp + (size_t)(q0 + lr + i * 16) * QKV_LD + ld4 * 4);
    {
        #pragma unroll
        for (int i = 0; i < 4; i++)
            cp_async16(&Ks[lr + i * 16][ld4 * 4],
                       Kp + (size_t)(lr + i * 16) * QKV_LD + ld4 * 4);
        CP_COMMIT();
    }
    issueV(0);

    float m0 = -1e30f, m1 = -1e30f, l0 = 0.f, l1 = 0.f;
    float oa[8][4];
    #pragma unroll
    for (int tj = 0; tj < 8; tj++)
        #pragma unroll
        for (int r = 0; r < 4; r++) oa[tj][r] = 0.f;

    for (int j = 0; j < 16; j++) {
        CP_WAIT(1);            // K_j (and Q on j=0) arrived; V_j still allowed in flight
        __syncthreads();

        // S = Q @ K^T (warp tile 16x64)
        float sa[8][4];
        #pragma unroll
        for (int tj = 0; tj < 8; tj++)
            #pragma unroll
            for (int r = 0; r < 4; r++) sa[tj][r] = 0.f;
        #pragma unroll
        for (int k8 = 0; k8 < 64; k8 += 8) {
            unsigned af[4];
            af[0] = __float_as_uint(Qs[warp_m + g][k8 + tg]);
            af[1] = __float_as_uint(Qs[warp_m + g + 8][k8 + tg]);
            af[2] = __float_as_uint(Qs[warp_m + g][k8 + tg + 4]);
            af[3] = __float_as_uint(Qs[warp_m + g + 8][k8 + tg + 4]);
            #pragma unroll
            for (int tj = 0; tj < 8; tj++) {
                unsigned bf[2];
                bf[0] = __float_as_uint(Ks[tj * 8 + g][k8 + tg]);
                bf[1] = __float_as_uint(Ks[tj * 8 + g][k8 + tg + 4]);
                mma_tf32(sa[tj], af, bf[0] == bf[0] ? bf : bf);
            }
        }

        // Online softmax (rows g and g+8 of warp tile)
        float mx0 = -1e30f, mx1 = -1e30f;
        #pragma unroll
        for (int tj = 0; tj < 8; tj++) {
            sa[tj][0] *= 0.125f; sa[tj][1] *= 0.125f;
            sa[tj][2] *= 0.125f; sa[tj][3] *= 0.125f;
            mx0 = fmaxf(mx0, fmaxf(sa[tj][0], sa[tj][1]));
            mx1 = fmaxf(mx1, fmaxf(sa[tj][2], sa[tj][3]));
        }
        mx0 = fmaxf(mx0, __shfl_xor_sync(0xffffffffu, mx0, 1));
        mx0 = fmaxf(mx0, __shfl_xor_sync(0xffffffffu, mx0, 2));
        mx1 = fmaxf(mx1, __shfl_xor_sync(0xffffffffu, mx1, 1));
        mx1 = fmaxf(mx1, __shfl_xor_sync(0xffffffffu, mx1, 2));
        float mn0 = fmaxf(m0, mx0), mn1 = fmaxf(m1, mx1);
        float a0 = __expf(m0 - mn0), a1 = __expf(m1 - mn1);
        float s0 = 0.f, s1 = 0.f;
        #pragma unroll
        for (int tj = 0; tj < 8; tj++) {
            float p0 = __expf(sa[tj][0] - mn0);
            float p1 = __expf(sa[tj][1] - mn0);
            float p2 = __expf(sa[tj][2] - mn1);
            float p3 = __expf(sa[tj][3] - mn1);
            s0 += p0 + p1; s1 += p2 + p3;
            Ps[warp_m + g][tj * 8 + 2 * tg]         = tf32f(p0);
            Ps[warp_m + g][tj * 8 + 2 * tg + 1]     = tf32f(p1);
            Ps[warp_m + g + 8][tj * 8 + 2 * tg]     = tf32f(p2);
            Ps[warp_m + g + 8][tj * 8 + 2 * tg + 1] = tf32f(p3);
            oa[tj][0] *= a0; oa[tj][1] *= a0;
            oa[tj][2] *= a1; oa[tj][3] *= a1;
        }
        s0 += __shfl_xor_sync(0xffffffffu, s0, 1);
        s0 += __shfl_xor_sync(0xffffffffu, s0, 2);
        s1 += __shfl_xor_sync(0xffffffffu, s1, 1);
        s1 += __shfl_xor_sync(0xffffffffu, s1, 2);
        l0 = l0 * a0 + s0; l1 = l1 * a1 + s1;
        m0 = mn0; m1 = mn1;

        __syncthreads();                 // all warps done with Ks; Ps visible
        if (j < 15) issueK(j + 1);       // overlap K load with PV
        if (j < 15) { CP_WAIT(1); } else { CP_WAIT(0); }   // V_j arrived
        __syncthreads();

        // O += P @ V
        #pragma unroll
        for (int k8 = 0; k8 < 64; k8 += 8) {
            unsigned af[4];
            af[0] = __float_as_uint(Ps[warp_m + g][k8 + tg]);
            af[1] = __float_as_uint(Ps[warp_m + g + 8][k8 + tg]);
            af[2] = __float_as_uint(Ps[warp_m + g][k8 + tg + 4]);
            af[3] = __float_as_uint(Ps[warp_m + g + 8][k8 + tg + 4]);
            #pragma unroll
            for (int tj = 0; tj < 8; tj++) {
                unsigned bf[2];
                bf[0] = __float_as_uint(Vs[k8 + tg][tj * 8 + g]);
                bf[1] = __float_as_uint(Vs[k8 + tg + 4][tj * 8 + g]);
                mma_tf32(oa[tj], af, bf);
            }
        }
        __syncthreads();                 // all warps done with Vs
        if (j < 15) issueV(j + 1);
    }

    // Normalize and write O[b][n][hd*64+d]
    float i0 = 1.f / l0, i1 = 1.f / l1;
    int r0 = q0 + warp_m + g, r1 = r0 + 8;
    float* Ob = O + (size_t)b * NN_TOK * INNER + hd * DH;
    #pragma unroll
    for (int tj = 0; tj < 8; tj++) {
        int cc = tj * 8 + 2 * tg;
        float2 v0 = {oa[tj][0] * i0, oa[tj][1] * i0};
        float2 v1 = {oa[tj][2] * i1, oa[tj][3] * i1};
        *(float2*)&Ob[(size_t)r0 * INNER + cc] = v0;
        *(float2*)&Ob[(size_t)r1 * INNER + cc] = v1;
    }
}

// ---------------------------------------------------------------------------
__global__ void copy_kernel(const float* __restrict__ src, float* __restrict__ dst) {
    int i = blockIdx.x * 256 + threadIdx.x;
    ((float4*)dst)[i] = ((const float4*)src)[i];
}

// ---------------------------------------------------------------------------
extern "C" void kernel_launch(void* const* d_in, const int* in_sizes, int n_in,
                              void* d_out, int out_size) {
    const float* x      = (const float*)d_in[0];
    const float* w_conv = (const float*)d_in[1];
    const float* b_conv = (const float*)d_in[2];
    const float* pos    = (const float*)d_in[3];
    const float* ln1_w  = (const float*)d_in[4];
    const float* ln1_b  = (const float*)d_in[5];
    const float* qkv_w  = (const float*)d_in[6];
    const float* out_w  = (const float*)d_in[7];
    const float* out_b  = (const float*)d_in[8];
    const float* ln2_w  = (const float*)d_in[9];
    const float* ln2_b  = (const float*)d_in[10];
    const float* w1     = (const float*)d_in[11];
    const float* b1     = (const float*)d_in[12];
    const float* w2     = (const float*)d_in[13];
    const float* b2     = (const float*)d_in[14];

    float *h, *y, *qkv, *o, *mlp;
    cudaGetSymbolAddress((void**)&h,   g_h);
    cudaGetSymbolAddress((void**)&y,   g_y);
    cudaGetSymbolAddress((void**)&qkv, g_qkv);
    cudaGetSymbolAddress((void**)&o,   g_o);
    cudaGetSymbolAddress((void**)&mlp, g_mlp);

    // Opt-in dynamic smem (idempotent; safe under graph capture)
    cudaFuncSetAttribute(mma_gemm<0,0,0,1>, cudaFuncAttributeMaxDynamicSharedMemorySize, GEMM_SMEM);
    cudaFuncSetAttribute(mma_gemm<1,0,1,0>, cudaFuncAttributeMaxDynamicSharedMemorySize, GEMM_SMEM);
    cudaFuncSetAttribute(mma_gemm<1,1,0,0>, cudaFuncAttributeMaxDynamicSharedMemorySize, GEMM_SMEM);
    cudaFuncSetAttribute(flash_attn,        cudaFuncAttributeMaxDynamicSharedMemorySize, FLASH_SMEM);

    patch_embed_kernel<<<M_ROWS, 256>>>(x, w_conv, b_conv, pos, h);

    for (int l = 0; l < DEPTH; l++) {
        const float* l1w = ln1_w + (size_t)l * DD;
        const float* l1b = ln1_b + (size_t)l * DD;
        const float* qw  = qkv_w + (size_t)l * DD * QKV_LD;
        const float* ow  = out_w + (size_t)l * INNER * DD;
        const float* ob  = out_b + (size_t)l * DD;
        const float* l2w = ln2_w + (size_t)l * DD;
        const float* l2b = ln2_b + (size_t)l * DD;
        const float* W1  = w1 + (size_t)l * DD * MLPD;
        const float* B1  = b1 + (size_t)l * MLPD;
        const float* W2  = w2 + (size_t)l * MLPD * DD;
        const float* B2  = b2 + (size_t)l * DD;

        // PreNorm + QKV projection (tf32-rounded output feeds attention)
        ln_kernel<<<M_ROWS, 256>>>(h, l1w, l1b, y);
        mma_gemm<0,0,0,1><<<dim3(QKV_LD / 128, M_ROWS / 128), 256, GEMM_SMEM>>>(
            y, qw, nullptr, nullptr, qkv, DD, QKV_LD);

        // Fused flash attention
        flash_attn<<<dim3(NN_TOK / 128, BB * HEADS), 256, FLASH_SMEM>>>(qkv, o);

        // Output projection + residual
        mma_gemm<1,0,1,0><<<dim3(DD / 128, M_ROWS / 128), 256, GEMM_SMEM>>>(
            o, ow, ob, h, h, INNER, DD);

        // PreNorm + FFN
        ln_kernel<<<M_ROWS, 256>>>(h, l2w, l2b, y);
        mma_gemm<1,1,0,0><<<dim3(MLPD / 128, M_ROWS / 128), 256, GEMM_SMEM>>>(
            y, W1, B1, nullptr, mlp, DD, MLPD);
        mma_gemm<1,0,1,0><<<dim3(DD / 128, M_ROWS / 128), 256, GEMM_SMEM>>>(
            mlp, W2, B2, h, h, MLPD, DD);
    }

    copy_kernel<<<(M_ROWS * DD) / (256 * 4), 256>>>(h, (float*)d_out);
}